// round 10
// baseline (speedup 1.0000x reference)
#include <cuda_runtime.h>

// Reference collapse (verified, rel_err 0.0): only the diagonal of the RBF
// self-Gram matrix reaches the output; fp32 diagonal sqdist is exactly
// xn - 2*xn + xn == 0.0f, so K[i,i] = exp(-gamma*0) == 1.0f bitwise. Every
// output element is the identical scalar
//   r = sum_h relu(exp(-gamma*0)*W1[h] + b1[h]) * W2[h] + b2.
//
// Inputs (metadata order): X[16384], gamma[1], W1[32], b1[32], W2[32], b2[1]
// Output: float32 [16384]
//
// Launch-floor bound. v8: 128 CTAs x 32 threads — one warp per CTA, one CTA
// per SM in wave 1, minimizing per-SM serial issue (24 uniform LDG.128
// wavefronts + 32 STG.128 per SM) and CTA-internal ramp.

__global__ void __launch_bounds__(32, 1)
qkr_kernel_v8(const float*  __restrict__ gamma,
              const float4* __restrict__ W1v,   // 8 x float4
              const float4* __restrict__ b1v,   // 8 x float4
              const float4* __restrict__ W2v,   // 8 x float4
              const float*  __restrict__ b2,
              float4* __restrict__ out4,
              int n4)
{
    int i = blockIdx.x * 32 + threadIdx.x;
    if (i >= n4) return;

    // Reference-faithful diagonal kernel value (sq == 0 exactly).
    float k = __expf(-gamma[0] * 0.0f);          // 1.0f unless gamma NaN/Inf

    // Front-batch all weight loads (independent warp-uniform LDG.128s).
    float4 w1[8], bb[8], w2[8];
    #pragma unroll
    for (int j = 0; j < 8; ++j) { w1[j] = W1v[j]; bb[j] = b1v[j]; w2[j] = W2v[j]; }

    // 4 independent accumulator chains, 8 FMA pairs deep each.
    float a0 = 0.0f, a1 = 0.0f, a2 = 0.0f, a3 = 0.0f;
    #pragma unroll
    for (int j = 0; j < 8; ++j) {
        float v;
        v = fmaxf(fmaf(k, w1[j].x, bb[j].x), 0.0f); a0 = fmaf(v, w2[j].x, a0);
        v = fmaxf(fmaf(k, w1[j].y, bb[j].y), 0.0f); a1 = fmaf(v, w2[j].y, a1);
        v = fmaxf(fmaf(k, w1[j].z, bb[j].z), 0.0f); a2 = fmaf(v, w2[j].z, a2);
        v = fmaxf(fmaf(k, w1[j].w, bb[j].w), 0.0f); a3 = fmaf(v, w2[j].w, a3);
    }
    float r = ((a0 + a1) + (a2 + a3)) + b2[0];

    out4[i] = make_float4(r, r, r, r);
}

extern "C" void kernel_launch(void* const* d_in, const int* in_sizes, int n_in,
                              void* d_out, int out_size)
{
    const float* gamma = (const float*)d_in[1];
    const float* W1    = (const float*)d_in[2];
    const float* b1    = (const float*)d_in[3];
    const float* W2    = (const float*)d_in[4];
    const float* b2    = (const float*)d_in[5];
    float* out = (float*)d_out;

    int n4 = out_size / 4;                       // 4096
    const int threads = 32;
    int blocks = (n4 + threads - 1) / threads;   // 128
    qkr_kernel_v8<<<blocks, threads>>>(gamma,
                                       (const float4*)W1, (const float4*)b1,
                                       (const float4*)W2, b2,
                                       (float4*)out, n4);
}

// round 13
// speedup vs baseline: 1.4648x; 1.4648x over previous
#include <cuda_runtime.h>

// Reference collapse (verified, rel_err 0.0): only the diagonal of the RBF
// self-Gram matrix reaches the output; fp32 diagonal sqdist is exactly
// xn - 2*xn + xn == 0.0f, so K[i,i] = exp(-gamma*0) == 1.0f bitwise. Every
// output element is the identical scalar
//   r = sum_h relu(exp(-gamma*0)*W1[h] + b1[h]) * W2[h] + b2.
//
// Inputs (metadata order): X[16384], gamma[1], W1[32], b1[32], W2[32], b2[1]
// Output: float32 [16384]
//
// Launch-floor bound (all pipes <1%). Grid-shape sweep measured:
//   16x256: 4.928us | 32x128: 4.288us | 64x64: 4.160us (BEST) | 128x32: 4.288us
// This is the measured-optimal 64 CTAs x 64 threads configuration.

__global__ void __launch_bounds__(64, 1)
qkr_kernel_v9(const float*  __restrict__ gamma,
              const float4* __restrict__ W1v,   // 8 x float4
              const float4* __restrict__ b1v,   // 8 x float4
              const float4* __restrict__ W2v,   // 8 x float4
              const float*  __restrict__ b2,
              float4* __restrict__ out4,
              int n4)
{
    int i = blockIdx.x * blockDim.x + threadIdx.x;
    if (i >= n4) return;

    // Reference-faithful diagonal kernel value (sq == 0 exactly).
    float k = __expf(-gamma[0] * 0.0f);          // 1.0f unless gamma NaN/Inf

    // Front-batch all weight loads (independent warp-uniform LDG.128s).
    float4 w1[8], bb[8], w2[8];
    #pragma unroll
    for (int j = 0; j < 8; ++j) { w1[j] = W1v[j]; bb[j] = b1v[j]; w2[j] = W2v[j]; }

    // 4 independent accumulator chains, 8 FMA pairs deep each.
    float a0 = 0.0f, a1 = 0.0f, a2 = 0.0f, a3 = 0.0f;
    #pragma unroll
    for (int j = 0; j < 8; ++j) {
        float v;
        v = fmaxf(fmaf(k, w1[j].x, bb[j].x), 0.0f); a0 = fmaf(v, w2[j].x, a0);
        v = fmaxf(fmaf(k, w1[j].y, bb[j].y), 0.0f); a1 = fmaf(v, w2[j].y, a1);
        v = fmaxf(fmaf(k, w1[j].z, bb[j].z), 0.0f); a2 = fmaf(v, w2[j].z, a2);
        v = fmaxf(fmaf(k, w1[j].w, bb[j].w), 0.0f); a3 = fmaf(v, w2[j].w, a3);
    }
    float r = ((a0 + a1) + (a2 + a3)) + b2[0];

    out4[i] = make_float4(r, r, r, r);
}

extern "C" void kernel_launch(void* const* d_in, const int* in_sizes, int n_in,
                              void* d_out, int out_size)
{
    const float* gamma = (const float*)d_in[1];
    const float* W1    = (const float*)d_in[2];
    const float* b1    = (const float*)d_in[3];
    const float* W2    = (const float*)d_in[4];
    const float* b2    = (const float*)d_in[5];
    float* out = (float*)d_out;

    int n4 = out_size / 4;                       // 4096
    const int threads = 64;
    int blocks = (n4 + threads - 1) / threads;   // 64
    qkr_kernel_v9<<<blocks, threads>>>(gamma,
                                       (const float4*)W1, (const float4*)b1,
                                       (const float4*)W2, b2,
                                       (float4*)out, n4);
}